// round 12
// baseline (speedup 1.0000x reference)
#include <cuda_runtime.h>
#include <cuda_bf16.h>
#include <math.h>

#define TPB  256
#define NBLK 592                      // 4 blocks/SM * 148 SMs -> all resident
#define GT   (NBLK * TPB)

// ---------------- scratch (static device globals; no allocation) ----------------
__device__ float g_t0A[2][786432];   // stage0 pass1 out
__device__ float g_t0B[2][196608];   // stage0 pass2 out
__device__ float g_r0[2][49152];     // stage0 resized [tensor][B=4][3][4096]
__device__ float g_t1A[2][393216];   // stage1 pass1 out
__device__ float g_t1B[2][49152];    // stage1 pass2 out
__device__ float g_r1[2][6144];      // stage1 resized [tensor][B=4][3][512]
__device__ unsigned long long g_k0[16384];  // stage0 argmin keys [B][4096]
__device__ unsigned long long g_k1[2048];   // stage1 argmin keys [B][512]
__device__ double g_acc[2];          // per-stage cos sums
__device__ unsigned g_bar;           // barrier arrival counter (self-resets)
__device__ unsigned g_gen;           // barrier generation (monotone across replays)
__device__ unsigned g_done;          // cos completion counter (reset each run)

// ---------------- grid-wide barrier (all NBLK blocks resident by construction) --
__device__ __forceinline__ void grid_sync() {
    __syncthreads();
    if (threadIdx.x == 0) {
        __threadfence();
        unsigned gen = atomicAdd(&g_gen, 0u);
        if (atomicAdd(&g_bar, 1u) == NBLK - 1u) {
            atomicExch(&g_bar, 0u);
            __threadfence();
            atomicAdd(&g_gen, 1u);                // release
        } else {
            while (atomicAdd(&g_gen, 0u) == gen) { }
        }
        __threadfence();
    }
    __syncthreads();
}

// ---------------- table-driven resize tap loop -----------------------------------
// Pre-normalized triangle weights (w/sum_w), matching jax compute_weight_mat.
template<int NT>
__device__ __forceinline__ float resize_tab(const float* __restrict__ src, int inner,
                                            const float* __restrict__ w, int jlo)
{
    const float* p = src + (size_t)jlo * inner;
    float acc = 0.0f;
#pragma unroll
    for (int k = 0; k < NT; ++k)
        acc = fmaf(w[k], p[(size_t)k * inner], acc);
    return acc;
}

// ---------------- nearest neighbor unit ----------------------------------------
// score = 0.5*|b|^2 - a.b (argmin-equivalent to |a-b|^2). Partial argmins over
// m-tiles merged via atomicMin on key (sortable float bits << 32) | m; lower m
// wins ties -> jnp.argmin first-occurrence semantics.
template<int N, int NPT, int NM>
__device__ __forceinline__ void nn_unit(const float* __restrict__ A,
                                        const float* __restrict__ Bp,
                                        unsigned long long* __restrict__ keys,
                                        int b, int ytile, int mtile, float4* sB)
{
    int m0 = mtile * NM;
    const float* bx = Bp + (size_t)b * 3 * N;
    for (int i = threadIdx.x; i < NM; i += TPB) {
        int m = m0 + i;
        float x = bx[m], y = bx[N + m], z = bx[2 * N + m];
        sB[i] = make_float4(x, y, z, 0.5f * (x * x + y * y + z * z));
    }
    __syncthreads();

    const float* ax = A + (size_t)b * 3 * N;
    int nb = ytile * (TPB * NPT) + threadIdx.x;

    float px[NPT], py[NPT], pz[NPT], best[NPT];
    int bm[NPT];
#pragma unroll
    for (int k = 0; k < NPT; ++k) {
        int n = nb + k * TPB;
        px[k] = ax[n]; py[k] = ax[N + n]; pz[k] = ax[2 * N + n];
        best[k] = 3.402823466e38f; bm[k] = 0;
    }

#pragma unroll 4
    for (int i = 0; i < NM; ++i) {
        float4 q = sB[i];
#pragma unroll
        for (int k = 0; k < NPT; ++k) {
            float s = fmaf(-px[k], q.x, q.w);
            s = fmaf(-py[k], q.y, s);
            s = fmaf(-pz[k], q.z, s);
            if (s < best[k]) { best[k] = s; bm[k] = i; }
        }
    }

#pragma unroll
    for (int k = 0; k < NPT; ++k) {
        int n = nb + k * TPB;
        unsigned u = __float_as_uint(best[k]);
        u = (u & 0x80000000u) ? ~u : (u | 0x80000000u);   // order-preserving map
        unsigned long long key = ((unsigned long long)u << 32) | (unsigned)(m0 + bm[k]);
        atomicMin(&keys[(size_t)b * N + n], key);
    }
}

// ---------------- cosine body ----------------------------------------------------
// desc layout [B][32][N]; flattened-spatial element (b,n,c) = desc[b,c,n].
template<int N>
__device__ __forceinline__ float cos_body(const float* __restrict__ sd,
                                          const float* __restrict__ td,
                                          const unsigned long long* __restrict__ keys,
                                          int b, int xb)
{
    int n = xb * TPB + threadIdx.x;
    int m = (int)(unsigned)(keys[(size_t)b * N + n] & 0xFFFFFFFFull);

    const float* s = sd + (size_t)b * 32 * N;
    const float* t = td + (size_t)b * 32 * N;
    float dot = 0.f, ns = 0.f, ng = 0.f;
#pragma unroll
    for (int c = 0; c < 32; ++c) {
        float x = s[(size_t)c * N + n];
        float y = t[(size_t)c * N + m];
        dot = fmaf(x, y, dot);
        ns  = fmaf(x, x, ns);
        ng  = fmaf(y, y, ng);
    }
    return dot / (fmaxf(sqrtf(ns), 1e-8f) * fmaxf(sqrtf(ng), 1e-8f));
}

// ---------------- the single persistent kernel ----------------------------------
__global__ void __launch_bounds__(TPB, 4)
mega_kernel(const float* __restrict__ cs,  const float* __restrict__ ct,
            const float* __restrict__ sd0, const float* __restrict__ td0,
            const float* __restrict__ sd1, const float* __restrict__ td1,
            float* __restrict__ out)
{
    __shared__ float4 sB[64];
    __shared__ float  wsum[TPB / 32];
    __shared__ float  s_w0[16 * 8];    // stage0 weights [i][k], prenormalized
    __shared__ float  s_w1[8 * 16];    // stage1 weights [i][k]
    __shared__ int    s_j0[16], s_j1[8];
    const int gid = blockIdx.x * TPB + threadIdx.x;

    // ---- weight tables (once per block; identical for all 3 passes) ----
    if (threadIdx.x < 24) {
        int stage = threadIdx.x >= 16;
        int i = stage ? threadIdx.x - 16 : threadIdx.x;
        float R    = stage ? 8.0f : 4.0f;
        float invR = stage ? 0.125f : 0.25f;
        int NT     = stage ? 16 : 8;
        float sf = (i + 0.5f) * R - 0.5f;
        int jlo = (int)floorf(sf - R) + 1;
        if (jlo < 0) jlo = 0;
        if (jlo > 64 - NT) jlo = 64 - NT;
        float wv[16]; float ws = 0.0f;
        for (int k = 0; k < NT; ++k) {
            float w = 1.0f - fabsf((float)(jlo + k) - sf) * invR;
            w = fmaxf(w, 0.0f);
            ws += w; wv[k] = w;
        }
        for (int k = 0; k < NT; ++k) {
            float wn = wv[k] / ws;
            if (stage) s_w1[i * 16 + k] = wn; else s_w0[i * 8 + k] = wn;
        }
        if (stage) s_j1[i] = jlo; else s_j0[i] = jlo;
    }

    // ---- phase 0: init keys / accumulators (no barrier needed before phase 1) ----
    for (int i = gid; i < 16384; i += GT) g_k0[i] = ~0ULL;
    for (int i = gid; i < 2048;  i += GT) g_k1[i] = ~0ULL;
    if (gid < 2) g_acc[gid] = 0.0;
    if (gid == 0) g_done = 0u;
    __syncthreads();                    // weight tables ready

    // ---- phase 1: resize innermost dim (W) ----
    {
        const int S0 = 786432, S1 = 393216;          // per tensor
        for (int idx = gid; idx < 2 * S0 + 2 * S1; idx += GT) {
            if (idx < 2 * S0) {
                int tensor = idx / S0, l = idx - tensor * S0;
                int i = l & 15, o = l >> 4;
                const float* in = (tensor ? ct : cs) + (size_t)o * 64;
                g_t0A[tensor][l] = resize_tab<8>(in, 1, s_w0 + i * 8, s_j0[i]);
            } else {
                int r = idx - 2 * S0;
                int tensor = r / S1, l = r - tensor * S1;
                int i = l & 7, o = l >> 3;
                const float* in = (tensor ? ct : cs) + (size_t)o * 64;
                g_t1A[tensor][l] = resize_tab<16>(in, 1, s_w1 + i * 16, s_j1[i]);
            }
        }
    }
    grid_sync();

    // ---- phase 2: resize H ----
    {
        const int S0 = 196608, S1 = 49152;
        for (int idx = gid; idx < 2 * S0 + 2 * S1; idx += GT) {
            if (idx < 2 * S0) {
                int tensor = idx / S0, l = idx - tensor * S0;
                int t = l & 15, i = (l >> 4) & 15, o = l >> 8;
                const float* in = g_t0A[tensor] + (size_t)o * 64 * 16 + t;
                g_t0B[tensor][l] = resize_tab<8>(in, 16, s_w0 + i * 8, s_j0[i]);
            } else {
                int r = idx - 2 * S0;
                int tensor = r / S1, l = r - tensor * S1;
                int t = l & 7, i = (l >> 3) & 7, o = l >> 6;
                const float* in = g_t1A[tensor] + (size_t)o * 64 * 8 + t;
                g_t1B[tensor][l] = resize_tab<16>(in, 8, s_w1 + i * 16, s_j1[i]);
            }
        }
    }
    grid_sync();

    // ---- phase 3: resize D ----
    {
        const int S0 = 49152, S1 = 6144;
        for (int idx = gid; idx < 2 * S0 + 2 * S1; idx += GT) {
            if (idx < 2 * S0) {
                int tensor = idx / S0, l = idx - tensor * S0;
                int t = l & 255, i = (l >> 8) & 15, o = l >> 12;
                const float* in = g_t0B[tensor] + (size_t)o * 64 * 256 + t;
                g_r0[tensor][l] = resize_tab<8>(in, 256, s_w0 + i * 8, s_j0[i]);
            } else {
                int r = idx - 2 * S0;
                int tensor = r / S1, l = r - tensor * S1;
                int t = l & 63, i = (l >> 6) & 7, o = l >> 9;
                const float* in = g_t1B[tensor] + (size_t)o * 64 * 64 + t;
                g_r1[tensor][l] = resize_tab<16>(in, 64, s_w1 + i * 16, s_j1[i]);
            }
        }
    }
    grid_sync();

    // ---- phase 4: nearest neighbor ----
    // stage0: 512 units = b(4) x ytile(2) x mtile(64), Nm=64, NPT=8
    // stage1: 32 units  = b(4) x mtile(8),             Nm=64, NPT=2
    {
        int u = blockIdx.x;
        if (u < 512) {
            nn_unit<4096, 8, 64>(g_r0[0], g_r0[1], g_k0,
                                 u & 3, (u >> 2) & 1, u >> 3, sB);
        } else if (u < 544) {
            int v = u - 512;
            nn_unit<512, 2, 64>(g_r1[0], g_r1[1], g_k1,
                                v & 3, 0, v >> 2, sB);
        }
    }
    grid_sync();

    // ---- phase 5: cosine + reduction + finalize (only 72 blocks; rest exit) ----
    {
        int u = blockIdx.x;
        if (u >= 72) return;
        int stage = (u < 64) ? 0 : 1;
        float cv;
        if (stage == 0) cv = cos_body<4096>(sd0, td0, g_k0, u & 3, u >> 2);
        else            cv = cos_body<512> (sd1, td1, g_k1, (u - 64) & 3, (u - 64) >> 2);

        for (int o = 16; o > 0; o >>= 1) cv += __shfl_down_sync(0xffffffffu, cv, o);
        if ((threadIdx.x & 31) == 0) wsum[threadIdx.x >> 5] = cv;
        __syncthreads();
        if (threadIdx.x < TPB / 32) {
            float v = wsum[threadIdx.x];
            for (int o = (TPB / 64); o > 0; o >>= 1) v += __shfl_down_sync(0xffu, v, o);
            if (threadIdx.x == 0) {
                atomicAdd(&g_acc[stage], (double)v);
                __threadfence();
                if (atomicAdd(&g_done, 1u) == 71u) {      // last cos block
                    double a0 = atomicAdd(&g_acc[0], 0.0);
                    double a1 = atomicAdd(&g_acc[1], 0.0);
                    double l0 = 1.0 - a0 / (4.0 * 4096.0);
                    double l1 = 1.0 - a1 / (4.0 * 512.0);
                    out[0] = (float)(0.5 * (l0 + l1));
                }
            }
        }
    }
}

// ---------------- launch (single kernel launch) ----------------------------------
extern "C" void kernel_launch(void* const* d_in, const int* in_sizes, int n_in,
                              void* d_out, int out_size)
{
    const float* cs  = (const float*)d_in[0];  // canonical_source [4,3,64,64,64]
    const float* ct  = (const float*)d_in[1];  // canonical_target
    const float* sd0 = (const float*)d_in[2];  // src_desc0 [4,32,16,16,16]
    const float* td0 = (const float*)d_in[3];
    const float* sd1 = (const float*)d_in[4];  // src_desc1 [4,32,8,8,8]
    const float* td1 = (const float*)d_in[5];
    float* out = (float*)d_out;

    mega_kernel<<<NBLK, TPB>>>(cs, ct, sd0, td0, sd1, td1, out);
}

// round 13
// speedup vs baseline: 1.0843x; 1.0843x over previous
#include <cuda_runtime.h>
#include <cuda_bf16.h>
#include <math.h>

#define TPB  256
#define NBLK 592                      // 4 blocks/SM * 148 SMs -> all resident
#define GT   (NBLK * TPB)

// ---------------- scratch (static device globals; no allocation) ----------------
__device__ float g_t0A[2][786432];   // stage0 pass1 out
__device__ float g_t0B[2][196608];   // stage0 pass2 out
__device__ float g_r0[2][49152];     // stage0 resized [tensor][B=4][3][4096]
__device__ float g_t1A[2][393216];   // stage1 pass1 out
__device__ float g_t1B[2][49152];    // stage1 pass2 out
__device__ float g_r1[2][6144];      // stage1 resized [tensor][B=4][3][512]
__device__ unsigned long long g_k0[16384];  // stage0 argmin keys [B][4096]
__device__ unsigned long long g_k1[2048];   // stage1 argmin keys [B][512]
__device__ double g_acc[2];          // per-stage cos sums
__device__ unsigned g_bar;           // barrier arrival counter (self-resets)
__device__ unsigned g_gen;           // barrier generation (monotone across replays)
__device__ unsigned g_done;          // cos completion counter (reset each run)

// ---------------- grid-wide barrier (all NBLK blocks resident by construction) --
__device__ __forceinline__ void grid_sync() {
    __syncthreads();
    if (threadIdx.x == 0) {
        __threadfence();
        unsigned gen = *(volatile unsigned*)&g_gen;
        if (atomicAdd(&g_bar, 1u) == NBLK - 1u) {
            atomicExch(&g_bar, 0u);
            __threadfence();
            atomicAdd(&g_gen, 1u);                // release
        } else {
            while (*(volatile unsigned*)&g_gen == gen) { }
        }
        __threadfence();
    }
    __syncthreads();
}

// ---------------- table-driven resize tap loop -----------------------------------
// Pre-normalized triangle weights (w/sum_w), matching jax compute_weight_mat.
template<int NT>
__device__ __forceinline__ float resize_tab(const float* __restrict__ src, int inner,
                                            const float* __restrict__ w, int jlo)
{
    const float* p = src + (size_t)jlo * inner;
    float acc = 0.0f;
#pragma unroll
    for (int k = 0; k < NT; ++k)
        acc = fmaf(w[k], p[(size_t)k * inner], acc);
    return acc;
}

// ---------------- nearest neighbor unit (packed fminf argmin) -------------------
// score = 0.5*|b|^2 - a.b (argmin-equivalent to |a-b|^2). Within a tile the
// 7 low mantissa bits of the score are replaced by the tile-local index i and
// the running min is a single fminf -> 5 instr/pair, no select chain, no index
// registers. Cross-tile merge via atomicMin on (sortable float bits << 32) | m;
// lower m wins ties, matching jnp.argmin first-occurrence semantics.
template<int N, int NPT, int NM>
__device__ __forceinline__ void nn_unit(const float* __restrict__ A,
                                        const float* __restrict__ Bp,
                                        unsigned long long* __restrict__ keys,
                                        int b, int ytile, int mtile, float4* sB)
{
    int m0 = mtile * NM;
    const float* bx = Bp + (size_t)b * 3 * N;
    for (int i = threadIdx.x; i < NM; i += TPB) {
        int m = m0 + i;
        float x = bx[m], y = bx[N + m], z = bx[2 * N + m];
        sB[i] = make_float4(x, y, z, 0.5f * (x * x + y * y + z * z));
    }
    __syncthreads();

    const float* ax = A + (size_t)b * 3 * N;
    int nb = ytile * (TPB * NPT) + threadIdx.x;

    float px[NPT], py[NPT], pz[NPT], best[NPT];
#pragma unroll
    for (int k = 0; k < NPT; ++k) {
        int n = nb + k * TPB;
        px[k] = ax[n]; py[k] = ax[N + n]; pz[k] = ax[2 * N + n];
        best[k] = 3.402823466e38f;                // 0x7F7FFFFF
    }

#pragma unroll 4
    for (int i = 0; i < NM; ++i) {
        float4 q = sB[i];
#pragma unroll
        for (int k = 0; k < NPT; ++k) {
            float s = fmaf(-px[k], q.x, q.w);
            s = fmaf(-py[k], q.y, s);
            s = fmaf(-pz[k], q.z, s);
            unsigned us = (__float_as_uint(s) & 0xFFFFFF80u) | (unsigned)i;  // LOP3
            best[k] = fminf(best[k], __uint_as_float(us));                    // FMNMX
        }
    }

#pragma unroll
    for (int k = 0; k < NPT; ++k) {
        int n = nb + k * TPB;
        unsigned u = __float_as_uint(best[k]);
        int i = (int)(u & 0x7Fu);
        unsigned su = (u & 0x80000000u) ? ~u : (u | 0x80000000u);  // order-preserving
        unsigned long long key = ((unsigned long long)su << 32) | (unsigned)(m0 + i);
        atomicMin(&keys[(size_t)b * N + n], key);
    }
}

// ---------------- cosine body ----------------------------------------------------
// desc layout [B][32][N]; flattened-spatial element (b,n,c) = desc[b,c,n].
template<int N>
__device__ __forceinline__ float cos_body(const float* __restrict__ sd,
                                          const float* __restrict__ td,
                                          const unsigned long long* __restrict__ keys,
                                          int b, int xb)
{
    int n = xb * TPB + threadIdx.x;
    int m = (int)(unsigned)(keys[(size_t)b * N + n] & 0xFFFFFFFFull);

    const float* s = sd + (size_t)b * 32 * N;
    const float* t = td + (size_t)b * 32 * N;
    float dot = 0.f, ns = 0.f, ng = 0.f;
#pragma unroll
    for (int c = 0; c < 32; ++c) {
        float x = s[(size_t)c * N + n];
        float y = t[(size_t)c * N + m];
        dot = fmaf(x, y, dot);
        ns  = fmaf(x, x, ns);
        ng  = fmaf(y, y, ng);
    }
    return dot / (fmaxf(sqrtf(ns), 1e-8f) * fmaxf(sqrtf(ng), 1e-8f));
}

// ---------------- the single persistent kernel ----------------------------------
__global__ void __launch_bounds__(TPB, 4)
mega_kernel(const float* __restrict__ cs,  const float* __restrict__ ct,
            const float* __restrict__ sd0, const float* __restrict__ td0,
            const float* __restrict__ sd1, const float* __restrict__ td1,
            float* __restrict__ out)
{
    __shared__ float4 sB[128];
    __shared__ float  wsum[TPB / 32];
    __shared__ float  s_w0[16 * 8];    // stage0 weights [i][k], prenormalized
    __shared__ float  s_w1[8 * 16];    // stage1 weights [i][k]
    __shared__ int    s_j0[16], s_j1[8];
    const int gid = blockIdx.x * TPB + threadIdx.x;

    // ---- weight tables (once per block; identical for all 3 passes) ----
    if (threadIdx.x < 24) {
        int stage = threadIdx.x >= 16;
        int i = stage ? threadIdx.x - 16 : threadIdx.x;
        float R    = stage ? 8.0f : 4.0f;
        float invR = stage ? 0.125f : 0.25f;
        int NT     = stage ? 16 : 8;
        float sf = (i + 0.5f) * R - 0.5f;
        int jlo = (int)floorf(sf - R) + 1;
        if (jlo < 0) jlo = 0;
        if (jlo > 64 - NT) jlo = 64 - NT;
        float wv[16]; float ws = 0.0f;
        for (int k = 0; k < NT; ++k) {
            float w = 1.0f - fabsf((float)(jlo + k) - sf) * invR;
            w = fmaxf(w, 0.0f);
            ws += w; wv[k] = w;
        }
        for (int k = 0; k < NT; ++k) {
            float wn = wv[k] / ws;
            if (stage) s_w1[i * 16 + k] = wn; else s_w0[i * 8 + k] = wn;
        }
        if (stage) s_j1[i] = jlo; else s_j0[i] = jlo;
    }

    // ---- phase 0: init keys / accumulators ----
    for (int i = gid; i < 16384; i += GT) g_k0[i] = ~0ULL;
    for (int i = gid; i < 2048;  i += GT) g_k1[i] = ~0ULL;
    if (gid < 2) g_acc[gid] = 0.0;
    if (gid == 0) g_done = 0u;
    __syncthreads();                    // weight tables ready

    // ---- phase 1: resize innermost dim (W) ----
    {
        const int S0 = 786432, S1 = 393216;          // per tensor
        for (int idx = gid; idx < 2 * S0 + 2 * S1; idx += GT) {
            if (idx < 2 * S0) {
                int tensor = idx / S0, l = idx - tensor * S0;
                int i = l & 15, o = l >> 4;
                const float* in = (tensor ? ct : cs) + (size_t)o * 64;
                g_t0A[tensor][l] = resize_tab<8>(in, 1, s_w0 + i * 8, s_j0[i]);
            } else {
                int r = idx - 2 * S0;
                int tensor = r / S1, l = r - tensor * S1;
                int i = l & 7, o = l >> 3;
                const float* in = (tensor ? ct : cs) + (size_t)o * 64;
                g_t1A[tensor][l] = resize_tab<16>(in, 1, s_w1 + i * 16, s_j1[i]);
            }
        }
    }
    grid_sync();

    // ---- phase 2: resize H ----
    {
        const int S0 = 196608, S1 = 49152;
        for (int idx = gid; idx < 2 * S0 + 2 * S1; idx += GT) {
            if (idx < 2 * S0) {
                int tensor = idx / S0, l = idx - tensor * S0;
                int t = l & 15, i = (l >> 4) & 15, o = l >> 8;
                const float* in = g_t0A[tensor] + (size_t)o * 64 * 16 + t;
                g_t0B[tensor][l] = resize_tab<8>(in, 16, s_w0 + i * 8, s_j0[i]);
            } else {
                int r = idx - 2 * S0;
                int tensor = r / S1, l = r - tensor * S1;
                int t = l & 7, i = (l >> 3) & 7, o = l >> 6;
                const float* in = g_t1A[tensor] + (size_t)o * 64 * 8 + t;
                g_t1B[tensor][l] = resize_tab<16>(in, 8, s_w1 + i * 16, s_j1[i]);
            }
        }
    }
    grid_sync();

    // ---- phase 3: resize D ----
    {
        const int S0 = 49152, S1 = 6144;
        for (int idx = gid; idx < 2 * S0 + 2 * S1; idx += GT) {
            if (idx < 2 * S0) {
                int tensor = idx / S0, l = idx - tensor * S0;
                int t = l & 255, i = (l >> 8) & 15, o = l >> 12;
                const float* in = g_t0B[tensor] + (size_t)o * 64 * 256 + t;
                g_r0[tensor][l] = resize_tab<8>(in, 256, s_w0 + i * 8, s_j0[i]);
            } else {
                int r = idx - 2 * S0;
                int tensor = r / S1, l = r - tensor * S1;
                int t = l & 63, i = (l >> 6) & 7, o = l >> 9;
                const float* in = g_t1B[tensor] + (size_t)o * 64 * 64 + t;
                g_r1[tensor][l] = resize_tab<16>(in, 64, s_w1 + i * 16, s_j1[i]);
            }
        }
    }
    grid_sync();

    // ---- phase 4: nearest neighbor ----
    // stage0: 512 units = b(4) x ytile(4) x mtile(32), NM=128, NPT=4
    // stage1: 32 units  = b(4) x mtile(8),             NM=64,  NPT=2
    {
        int u = blockIdx.x;
        if (u < 512) {
            nn_unit<4096, 4, 128>(g_r0[0], g_r0[1], g_k0,
                                  u & 3, (u >> 2) & 3, u >> 4, sB);
        } else if (u < 544) {
            int v = u - 512;
            nn_unit<512, 2, 64>(g_r1[0], g_r1[1], g_k1,
                                v & 3, 0, v >> 2, sB);
        }
    }
    grid_sync();

    // ---- phase 5: cosine + reduction + finalize (only 72 blocks; rest exit) ----
    {
        int u = blockIdx.x;
        if (u >= 72) return;
        int stage = (u < 64) ? 0 : 1;
        float cv;
        if (stage == 0) cv = cos_body<4096>(sd0, td0, g_k0, u & 3, u >> 2);
        else            cv = cos_body<512> (sd1, td1, g_k1, (u - 64) & 3, (u - 64) >> 2);

        for (int o = 16; o > 0; o >>= 1) cv += __shfl_down_sync(0xffffffffu, cv, o);
        if ((threadIdx.x & 31) == 0) wsum[threadIdx.x >> 5] = cv;
        __syncthreads();
        if (threadIdx.x < TPB / 32) {
            float v = wsum[threadIdx.x];
            for (int o = (TPB / 64); o > 0; o >>= 1) v += __shfl_down_sync(0xffu, v, o);
            if (threadIdx.x == 0) {
                atomicAdd(&g_acc[stage], (double)v);
                __threadfence();
                if (atomicAdd(&g_done, 1u) == 71u) {      // last cos block
                    double a0 = atomicAdd(&g_acc[0], 0.0);
                    double a1 = atomicAdd(&g_acc[1], 0.0);
                    double l0 = 1.0 - a0 / (4.0 * 4096.0);
                    double l1 = 1.0 - a1 / (4.0 * 512.0);
                    out[0] = (float)(0.5 * (l0 + l1));
                }
            }
        }
    }
}

// ---------------- launch (single kernel launch) ----------------------------------
extern "C" void kernel_launch(void* const* d_in, const int* in_sizes, int n_in,
                              void* d_out, int out_size)
{
    const float* cs  = (const float*)d_in[0];  // canonical_source [4,3,64,64,64]
    const float* ct  = (const float*)d_in[1];  // canonical_target
    const float* sd0 = (const float*)d_in[2];  // src_desc0 [4,32,16,16,16]
    const float* td0 = (const float*)d_in[3];
    const float* sd1 = (const float*)d_in[4];  // src_desc1 [4,32,8,8,8]
    const float* td1 = (const float*)d_in[5];
    float* out = (float*)d_out;

    mega_kernel<<<NBLK, TPB>>>(cs, ct, sd0, td0, sd1, td1, out);
}